// round 1
// baseline (speedup 1.0000x reference)
#include <cuda_runtime.h>

// GatingFeatureExtractor: p[B, E=8, C=1000] fp32 -> feats[B, E*C + 3E + 5] fp32.
// Single-pass fused kernel: one CTA per batch row, each element of p read once,
// written once. All statistics accumulated in registers with O(E) state via:
//   - prefix-sum trick for sum_{i<j} p_i * logp_j  (pairwise KL)
//   - one-pass variance (sumsq - E*m^2)/(E-1)
//   - butterfly-shuffle top-2 merge for confidence/margin/argmax.

#define EPS_F 1e-8f

constexpr int E = 8;
constexpr int C = 1000;
constexpr int OUTW = E * C + 3 * E + 5;  // 8029
constexpr int NTHREADS = 256;
constexpr int NWARPS = NTHREADS / 32;

__global__ __launch_bounds__(NTHREADS)
void gating_feats_kernel(const float* __restrict__ pin, float* __restrict__ out)
{
    const int b = blockIdx.x;
    const float* __restrict__ pr = pin + (size_t)b * (E * C);
    float* __restrict__ orow = out + (size_t)b * OUTW;
    const int tid = threadIdx.x;

    float plogp[E], mx1[E], mx2[E];
    int ix1[E];
#pragma unroll
    for (int e = 0; e < E; e++) { plogp[e] = 0.f; mx1[e] = -1.f; mx2[e] = -1.f; ix1[e] = 0; }
    float s_cross = 0.f;   // sum_c sum_{i<j} p_i[c] * logp_j[c]
    float s_mixent = 0.f;  // -sum_c m_c * log(m_c + eps)
    float s_var = 0.f;     // sum_c var_c (ddof=1)

    for (int c = tid; c < C; c += NTHREADS) {
        float pv[E], lp[E];
#pragma unroll
        for (int e = 0; e < E; e++) pv[e] = __ldg(pr + e * C + c);
#pragma unroll
        for (int e = 0; e < E; e++) lp[e] = __logf(pv[e] + EPS_F);
#pragma unroll
        for (int e = 0; e < E; e++) orow[e * C + c] = pv[e];  // feats[:, :E*C] = p

        float sum = 0.f, sumsq = 0.f, pre = 0.f;
#pragma unroll
        for (int e = 0; e < E; e++) {
            plogp[e] = fmaf(pv[e], lp[e], plogp[e]);
            if (pv[e] > mx1[e]) { mx2[e] = mx1[e]; mx1[e] = pv[e]; ix1[e] = c; }
            else if (pv[e] > mx2[e]) { mx2[e] = pv[e]; }
            // prefix trick: sum_{i<j} p_i * lp_j  ==  sum_j lp_j * (sum_{i<j} p_i)
            s_cross = fmaf(lp[e], pre, s_cross);
            pre += pv[e];
            sum += pv[e];
            sumsq = fmaf(pv[e], pv[e], sumsq);
        }
        float m = sum * (1.0f / E);
        s_mixent = fmaf(-m, __logf(m + EPS_F), s_mixent);
        s_var = fmaf(sumsq - (float)E * m * m, 1.0f / (float)(E - 1), s_var);
    }

    // -------- intra-warp butterfly reduction --------
#pragma unroll
    for (int off = 16; off; off >>= 1) {
#pragma unroll
        for (int e = 0; e < E; e++) {
            plogp[e] += __shfl_xor_sync(0xffffffffu, plogp[e], off);
            float o1 = __shfl_xor_sync(0xffffffffu, mx1[e], off);
            float o2 = __shfl_xor_sync(0xffffffffu, mx2[e], off);
            int   oi = __shfl_xor_sync(0xffffffffu, ix1[e], off);
            if (o1 > mx1[e] || (o1 == mx1[e] && oi < ix1[e])) {
                mx2[e] = fmaxf(mx1[e], o2);
                mx1[e] = o1; ix1[e] = oi;
            } else {
                mx2[e] = fmaxf(mx2[e], o1);
            }
        }
        s_cross  += __shfl_xor_sync(0xffffffffu, s_cross, off);
        s_mixent += __shfl_xor_sync(0xffffffffu, s_mixent, off);
        s_var    += __shfl_xor_sync(0xffffffffu, s_var, off);
    }

    // -------- cross-warp reduction via shared memory --------
    __shared__ float sh_plogp[NWARPS][E];
    __shared__ float sh_mx1[NWARPS][E];
    __shared__ float sh_mx2[NWARPS][E];
    __shared__ int   sh_ix1[NWARPS][E];
    __shared__ float sh_scal[NWARPS][3];

    const int wid = tid >> 5, lid = tid & 31;
    if (lid == 0) {
#pragma unroll
        for (int e = 0; e < E; e++) {
            sh_plogp[wid][e] = plogp[e];
            sh_mx1[wid][e]   = mx1[e];
            sh_mx2[wid][e]   = mx2[e];
            sh_ix1[wid][e]   = ix1[e];
        }
        sh_scal[wid][0] = s_cross;
        sh_scal[wid][1] = s_mixent;
        sh_scal[wid][2] = s_var;
    }
    __syncthreads();

    if (tid == 0) {
        for (int w = 1; w < NWARPS; w++) {
#pragma unroll
            for (int e = 0; e < E; e++) {
                sh_plogp[0][e] += sh_plogp[w][e];
                float o1 = sh_mx1[w][e], o2 = sh_mx2[w][e];
                int oi = sh_ix1[w][e];
                if (o1 > sh_mx1[0][e] || (o1 == sh_mx1[0][e] && oi < sh_ix1[0][e])) {
                    sh_mx2[0][e] = fmaxf(sh_mx1[0][e], o2);
                    sh_mx1[0][e] = o1; sh_ix1[0][e] = oi;
                } else {
                    sh_mx2[0][e] = fmaxf(sh_mx2[0][e], o1);
                }
            }
            sh_scal[0][0] += sh_scal[w][0];
            sh_scal[0][1] += sh_scal[w][1];
            sh_scal[0][2] += sh_scal[w][2];
        }

        float sum_pl = 0.f, wsum = 0.f;
        int args[E];
#pragma unroll
        for (int e = 0; e < E; e++) {
            float pl = sh_plogp[0][e];
            orow[E * C + e]         = -pl;                          // expert_entropy
            orow[E * C + E + e]     = sh_mx1[0][e];                 // expert_confidence
            orow[E * C + 2 * E + e] = sh_mx1[0][e] - sh_mx2[0][e];  // expert_margin
            sum_pl += pl;
            wsum = fmaf(pl, (float)(E - 1 - e), wsum);
            args[e] = sh_ix1[0][e];
        }

        // disagreement: sort 8 argmax indices, count unique
        for (int i = 1; i < E; i++) {
            int key = args[i]; int j = i - 1;
            while (j >= 0 && args[j] > key) { args[j + 1] = args[j]; j--; }
            args[j + 1] = key;
        }
        int nuniq = 1;
        for (int i = 1; i < E; i++) nuniq += (args[i] != args[i - 1]) ? 1 : 0;

        const float Sx = sh_scal[0][0];
        const float mixent = sh_scal[0][1];
        const float varsum = sh_scal[0][2];
        const int n_pairs = E * (E - 1) / 2;

        orow[E * C + 3 * E + 0] = (float)(nuniq - 1) / (float)(E - 1);   // disagreement_ratio
        orow[E * C + 3 * E + 1] = (wsum - Sx) / (float)n_pairs;          // mean_pairwise_kl
        orow[E * C + 3 * E + 2] = mixent;                                // mixture_entropy
        orow[E * C + 3 * E + 3] = varsum / (float)C;                     // post_var
        orow[E * C + 3 * E + 4] = mixent + sum_pl / (float)E;            // mutual_info
    }
}

extern "C" void kernel_launch(void* const* d_in, const int* in_sizes, int n_in,
                              void* d_out, int out_size)
{
    const float* p = (const float*)d_in[0];
    float* out = (float*)d_out;
    const int B = in_sizes[0] / (E * C);   // 8192 for this problem's shapes
    gating_feats_kernel<<<B, NTHREADS>>>(p, out);
}

// round 2
// speedup vs baseline: 1.5124x; 1.5124x over previous
#include <cuda_runtime.h>
#include <cstdint>

// GatingFeatureExtractor: p[B, E=8, C=1000] fp32 -> feats[B, E*C + 3E + 5] fp32.
// Phased smem-staged kernel, one CTA per batch row:
//   A: cp.async gmem row -> smem (32KB)
//   B: warp w = expert w: plogp + top2/argmax (4 regs of state/thread)
//   C: all threads: per-class cross-expert stats (3 scalar accumulators)
//   D: alignment-fixed vectorized copy smem -> out (STG.128 body)
//   F: thread 0 finalizes the 29 stat columns.

#define EPS_F 1e-8f

constexpr int E = 8;
constexpr int C = 1000;
constexpr int EC = E * C;                  // 8000
constexpr int OUTW = EC + 3 * E + 5;       // 8029
constexpr int NT = 256;
constexpr int NW = NT / 32;

__device__ __forceinline__ void cp_async16(uint32_t saddr, const void* gptr) {
    asm volatile("cp.async.cg.shared.global [%0], [%1], 16;\n" ::"r"(saddr), "l"(gptr));
}

__global__ __launch_bounds__(NT)
void gating_feats_kernel(const float* __restrict__ pin, float* __restrict__ out)
{
    __shared__ float sp[EC];                       // raw posteriors for this row
    __shared__ float sh_plogp[E], sh_mx1[E], sh_mx2[E];
    __shared__ int   sh_ix1[E];
    __shared__ float sh_scal[NW][3];

    const int b   = blockIdx.x;
    const int tid = threadIdx.x;
    const int wid = tid >> 5;
    const int lane = tid & 31;

    const float* __restrict__ pr = pin + (size_t)b * EC;
    float* __restrict__ orow = out + (size_t)b * OUTW;

    // ---------------- Phase A: stage row into smem via cp.async ----------------
    if (tid < C / 4) {                              // 250 threads, 8 x 16B each
        uint32_t sbase = (uint32_t)__cvta_generic_to_shared(sp) + 16u * (uint32_t)tid;
#pragma unroll
        for (int e = 0; e < E; e++)
            cp_async16(sbase + (uint32_t)(e * C * 4), pr + e * C + 4 * tid);
    }
    asm volatile("cp.async.commit_group;\n" ::: "memory");
    asm volatile("cp.async.wait_group 0;\n" ::: "memory");
    __syncthreads();

    // ---------------- Phase B: per-expert stats (warp = expert) ----------------
    {
        const float* __restrict__ row = sp + wid * C;
        float pl = 0.f, m1 = -1.f, m2 = -1.f;
        int i1 = 0;
#pragma unroll 4
        for (int c = lane; c < C; c += 32) {
            float f = row[c];
            pl = fmaf(f, __logf(f + EPS_F), pl);
            if (f > m1) { m2 = m1; m1 = f; i1 = c; }
            else        { m2 = fmaxf(m2, f); }
        }
#pragma unroll
        for (int off = 16; off; off >>= 1) {
            pl += __shfl_xor_sync(0xffffffffu, pl, off);
            float o1 = __shfl_xor_sync(0xffffffffu, m1, off);
            float o2 = __shfl_xor_sync(0xffffffffu, m2, off);
            int   oi = __shfl_xor_sync(0xffffffffu, i1, off);
            if (o1 > m1 || (o1 == m1 && oi < i1)) {
                m2 = fmaxf(m1, o2); m1 = o1; i1 = oi;
            } else {
                m2 = fmaxf(m2, o1);
            }
        }
        if (lane == 0) {
            sh_plogp[wid] = pl; sh_mx1[wid] = m1; sh_mx2[wid] = m2; sh_ix1[wid] = i1;
        }
    }

    // ---------------- Phase C: cross-expert per-class stats ----------------
    {
        float s_cross = 0.f, s_mixent = 0.f, s_var = 0.f;
        for (int c = tid; c < C; c += NT) {
            float sum = 0.f, sumsq = 0.f, pre = 0.f;
#pragma unroll
            for (int e = 0; e < E; e++) {
                float f = sp[e * C + c];
                float lg = __logf(f + EPS_F);
                s_cross = fmaf(lg, pre, s_cross);   // sum_{i<j} p_i * logp_j
                pre += f;
                sum += f;
                sumsq = fmaf(f, f, sumsq);
            }
            float m = sum * (1.0f / E);
            s_mixent = fmaf(-m, __logf(m + EPS_F), s_mixent);
            s_var = fmaf(sumsq - (float)E * m * m, 1.0f / (float)(E - 1), s_var);
        }
#pragma unroll
        for (int off = 16; off; off >>= 1) {
            s_cross  += __shfl_xor_sync(0xffffffffu, s_cross, off);
            s_mixent += __shfl_xor_sync(0xffffffffu, s_mixent, off);
            s_var    += __shfl_xor_sync(0xffffffffu, s_var, off);
        }
        if (lane == 0) {
            sh_scal[wid][0] = s_cross; sh_scal[wid][1] = s_mixent; sh_scal[wid][2] = s_var;
        }
    }

    // ---------------- Phase D: copy smem -> out with aligned STG.128 ----------------
    {
        // out row base (in floats) is only guaranteed 4B aligned: fix up head/tail.
        const int base_mod = (int)(((size_t)b * OUTW) & 3);      // floats past 16B boundary
        const int h = (4 - base_mod) & 3;                        // head scalars
        const int nvec = (EC - h) >> 2;                          // aligned float4 chunks
        const int tail = (EC - h) & 3;
        if (tid < h)    orow[tid] = sp[tid];
        if (tid < tail) orow[h + 4 * nvec + tid] = sp[h + 4 * nvec + tid];
        const float* __restrict__ src = sp + h;
        float* __restrict__ dst = orow + h;
        for (int j = tid; j < nvec; j += NT) {
            float4 v;
            v.x = src[4 * j + 0]; v.y = src[4 * j + 1];
            v.z = src[4 * j + 2]; v.w = src[4 * j + 3];
            *reinterpret_cast<float4*>(dst + 4 * j) = v;
        }
    }

    __syncthreads();

    // ---------------- Finalize: 29 stat columns ----------------
    if (tid == 0) {
        float sum_pl = 0.f, wsum = 0.f;
        int args[E];
#pragma unroll
        for (int e = 0; e < E; e++) {
            float pl = sh_plogp[e];
            orow[EC + e]         = -pl;                      // expert_entropy
            orow[EC + E + e]     = sh_mx1[e];                // expert_confidence
            orow[EC + 2 * E + e] = sh_mx1[e] - sh_mx2[e];    // expert_margin
            sum_pl += pl;
            wsum = fmaf(pl, (float)(E - 1 - e), wsum);
            args[e] = sh_ix1[e];
        }

        // disagreement: sort 8 argmax indices, count unique
        for (int i = 1; i < E; i++) {
            int key = args[i]; int j = i - 1;
            while (j >= 0 && args[j] > key) { args[j + 1] = args[j]; j--; }
            args[j + 1] = key;
        }
        int nuniq = 1;
        for (int i = 1; i < E; i++) nuniq += (args[i] != args[i - 1]) ? 1 : 0;

        float Sx = 0.f, mixent = 0.f, varsum = 0.f;
        for (int w = 0; w < NW; w++) {
            Sx     += sh_scal[w][0];
            mixent += sh_scal[w][1];
            varsum += sh_scal[w][2];
        }
        const int n_pairs = E * (E - 1) / 2;

        orow[EC + 3 * E + 0] = (float)(nuniq - 1) / (float)(E - 1);  // disagreement_ratio
        orow[EC + 3 * E + 1] = (wsum - Sx) / (float)n_pairs;         // mean_pairwise_kl
        orow[EC + 3 * E + 2] = mixent;                               // mixture_entropy
        orow[EC + 3 * E + 3] = varsum / (float)C;                    // post_var
        orow[EC + 3 * E + 4] = mixent + sum_pl / (float)E;           // mutual_info
    }
}

extern "C" void kernel_launch(void* const* d_in, const int* in_sizes, int n_in,
                              void* d_out, int out_size)
{
    const float* p = (const float*)d_in[0];
    float* out = (float*)d_out;
    const int B = in_sizes[0] / EC;    // 8192 for this problem's shapes
    gating_feats_kernel<<<B, NT>>>(p, out);
}

// round 3
// speedup vs baseline: 1.6877x; 1.1159x over previous
#include <cuda_runtime.h>
#include <cstdint>

// GatingFeatureExtractor: p[B, E=8, C=1000] fp32 -> feats[B, E*C + 3E + 5] fp32.
// Phased smem-staged kernel, one CTA per batch row:
//   A: cp.async gmem row -> smem (32KB)
//   B: warp w = expert w: top2/argmax only (float4 LDS, no MUFU)
//   C: thread j owns classes 4j..4j+3: plogp[8], prefix-KL cross, mixture
//      entropy, variance -- all from conflict-free LDS.128, single pass
//   D: copy smem -> out with aligned STG.128; uniform row-shift h handled by
//      two overlapping aligned LDS.128 + component select (no bank conflicts)
//   F: thread 0 finalizes the 29 stat columns.

#define EPS_F 1e-8f

constexpr int E = 8;
constexpr int C = 1000;
constexpr int EC = E * C;                  // 8000
constexpr int OUTW = EC + 3 * E + 5;       // 8029
constexpr int NT = 256;
constexpr int NW = NT / 32;

__device__ __forceinline__ void cp_async16(uint32_t saddr, const void* gptr) {
    asm volatile("cp.async.cg.shared.global [%0], [%1], 16;\n" ::"r"(saddr), "l"(gptr));
}

__global__ __launch_bounds__(NT)
void gating_feats_kernel(const float* __restrict__ pin, float* __restrict__ out)
{
    __shared__ __align__(16) float sp[EC + 4];     // +4 pad: Phase D overlapping read
    __shared__ float sh_mx1[E], sh_mx2[E];
    __shared__ int   sh_ix1[E];
    __shared__ float sh_red[NW][11];               // plogp[8], cross, mixent, var

    const int b    = blockIdx.x;
    const int tid  = threadIdx.x;
    const int wid  = tid >> 5;
    const int lane = tid & 31;

    const float* __restrict__ pr = pin + (size_t)b * EC;
    float* __restrict__ orow = out + (size_t)b * OUTW;

    // ---------------- Phase A: stage row into smem via cp.async ----------------
    if (tid < C / 4) {                              // 250 threads, 8 x 16B each
        uint32_t sbase = (uint32_t)__cvta_generic_to_shared(sp) + 16u * (uint32_t)tid;
#pragma unroll
        for (int e = 0; e < E; e++)
            cp_async16(sbase + (uint32_t)(e * C * 4), pr + e * C + 4 * tid);
    }
    asm volatile("cp.async.commit_group;\n" ::: "memory");
    asm volatile("cp.async.wait_group 0;\n" ::: "memory");
    __syncthreads();

    // ---------------- Phase B: per-expert top2/argmax (warp = expert) ----------------
    {
        const float4* __restrict__ row4 = reinterpret_cast<const float4*>(sp + wid * C);
        float m1 = -1.f, m2 = -1.f;
        int i1 = 0;
#pragma unroll
        for (int k = 0; k < 8; k++) {
            int idx = lane + 32 * k;
            if (idx < C / 4) {
                float4 v = row4[idx];
                float vv[4] = {v.x, v.y, v.z, v.w};
#pragma unroll
                for (int i = 0; i < 4; i++) {
                    float f = vv[i];
                    if (f > m1) { m2 = m1; m1 = f; i1 = 4 * idx + i; }
                    else        { m2 = fmaxf(m2, f); }
                }
            }
        }
#pragma unroll
        for (int off = 16; off; off >>= 1) {
            float o1 = __shfl_xor_sync(0xffffffffu, m1, off);
            float o2 = __shfl_xor_sync(0xffffffffu, m2, off);
            int   oi = __shfl_xor_sync(0xffffffffu, i1, off);
            if (o1 > m1 || (o1 == m1 && oi < i1)) {
                m2 = fmaxf(m1, o2); m1 = o1; i1 = oi;
            } else {
                m2 = fmaxf(m2, o1);
            }
        }
        if (lane == 0) { sh_mx1[wid] = m1; sh_mx2[wid] = m2; sh_ix1[wid] = i1; }
    }

    // ---------------- Phase C: single-pass cross-expert + plogp ----------------
    {
        float plogp[E];
#pragma unroll
        for (int e = 0; e < E; e++) plogp[e] = 0.f;
        float s_cross = 0.f, s_mixent = 0.f, s_var = 0.f;

        if (tid < C / 4) {                          // thread owns classes 4*tid..4*tid+3
            float pre[4] = {0.f, 0.f, 0.f, 0.f};
            float sum[4] = {0.f, 0.f, 0.f, 0.f};
            float ssq[4] = {0.f, 0.f, 0.f, 0.f};
#pragma unroll
            for (int e = 0; e < E; e++) {
                float4 v = reinterpret_cast<const float4*>(sp + e * C)[tid];
                float vv[4] = {v.x, v.y, v.z, v.w};
                float pe = 0.f;
#pragma unroll
                for (int i = 0; i < 4; i++) {
                    float f = vv[i];
                    float lg = __logf(f + EPS_F);
                    pe = fmaf(f, lg, pe);
                    s_cross = fmaf(lg, pre[i], s_cross);  // sum_{i<j} p_i * logp_j
                    pre[i] += f;
                    sum[i] += f;
                    ssq[i] = fmaf(f, f, ssq[i]);
                }
                plogp[e] = pe;
            }
#pragma unroll
            for (int i = 0; i < 4; i++) {
                float m = sum[i] * (1.0f / E);
                s_mixent = fmaf(-m, __logf(m + EPS_F), s_mixent);
                s_var = fmaf(ssq[i] - (float)E * m * m, 1.0f / (float)(E - 1), s_var);
            }
        }
#pragma unroll
        for (int off = 16; off; off >>= 1) {
#pragma unroll
            for (int e = 0; e < E; e++)
                plogp[e] += __shfl_xor_sync(0xffffffffu, plogp[e], off);
            s_cross  += __shfl_xor_sync(0xffffffffu, s_cross, off);
            s_mixent += __shfl_xor_sync(0xffffffffu, s_mixent, off);
            s_var    += __shfl_xor_sync(0xffffffffu, s_var, off);
        }
        if (lane == 0) {
#pragma unroll
            for (int e = 0; e < E; e++) sh_red[wid][e] = plogp[e];
            sh_red[wid][8] = s_cross; sh_red[wid][9] = s_mixent; sh_red[wid][10] = s_var;
        }
    }

    // ---------------- Phase D: copy smem -> out, aligned STG.128 ----------------
    {
        // (b*OUTW)%4 == b%4 since OUTW%4==1. dst vector frame starts at h.
        const int h = (4 - (b & 3)) & 3;
        const float4* __restrict__ sp4 = reinterpret_cast<const float4*>(sp);
        if (h == 0) {
            float4* __restrict__ dst4 = reinterpret_cast<float4*>(orow);
            for (int j = tid; j < EC / 4; j += NT) dst4[j] = sp4[j];
        } else {
            const int nvec = (EC - h) >> 2;
            const int tail = (EC - h) & 3;
            if (tid < h)    orow[tid] = sp[tid];
            if (tid < tail) orow[h + 4 * nvec + tid] = sp[h + 4 * nvec + tid];
            float4* __restrict__ dst4 = reinterpret_cast<float4*>(orow + h);
            for (int j = tid; j < nvec; j += NT) {
                float4 v = sp4[j];         // aligned, conflict-free
                float4 w = sp4[j + 1];     // overlap read (sp padded)
                float4 o;
                if (h == 1)      { o.x = v.y; o.y = v.z; o.z = v.w; o.w = w.x; }
                else if (h == 2) { o.x = v.z; o.y = v.w; o.z = w.x; o.w = w.y; }
                else             { o.x = v.w; o.y = w.x; o.z = w.y; o.w = w.z; }
                dst4[j] = o;
            }
        }
    }

    __syncthreads();

    // ---------------- Finalize: 29 stat columns ----------------
    if (tid == 0) {
        float plogp[E];
        float Sx = 0.f, mixent = 0.f, varsum = 0.f;
#pragma unroll
        for (int e = 0; e < E; e++) plogp[e] = 0.f;
        for (int w = 0; w < NW; w++) {
#pragma unroll
            for (int e = 0; e < E; e++) plogp[e] += sh_red[w][e];
            Sx     += sh_red[w][8];
            mixent += sh_red[w][9];
            varsum += sh_red[w][10];
        }

        float sum_pl = 0.f, wsum = 0.f;
        int args[E];
#pragma unroll
        for (int e = 0; e < E; e++) {
            float pl = plogp[e];
            orow[EC + e]         = -pl;                      // expert_entropy
            orow[EC + E + e]     = sh_mx1[e];                // expert_confidence
            orow[EC + 2 * E + e] = sh_mx1[e] - sh_mx2[e];    // expert_margin
            sum_pl += pl;
            wsum = fmaf(pl, (float)(E - 1 - e), wsum);
            args[e] = sh_ix1[e];
        }

        // disagreement: sort 8 argmax indices, count unique
        for (int i = 1; i < E; i++) {
            int key = args[i]; int j = i - 1;
            while (j >= 0 && args[j] > key) { args[j + 1] = args[j]; j--; }
            args[j + 1] = key;
        }
        int nuniq = 1;
        for (int i = 1; i < E; i++) nuniq += (args[i] != args[i - 1]) ? 1 : 0;

        const int n_pairs = E * (E - 1) / 2;
        orow[EC + 3 * E + 0] = (float)(nuniq - 1) / (float)(E - 1);  // disagreement_ratio
        orow[EC + 3 * E + 1] = (wsum - Sx) / (float)n_pairs;         // mean_pairwise_kl
        orow[EC + 3 * E + 2] = mixent;                               // mixture_entropy
        orow[EC + 3 * E + 3] = varsum / (float)C;                    // post_var
        orow[EC + 3 * E + 4] = mixent + sum_pl / (float)E;           // mutual_info
    }
}

extern "C" void kernel_launch(void* const* d_in, const int* in_sizes, int n_in,
                              void* d_out, int out_size)
{
    const float* p = (const float*)d_in[0];
    float* out = (float*)d_out;
    const int B = in_sizes[0] / EC;    // 8192 for this problem's shapes
    gating_feats_kernel<<<B, NT>>>(p, out);
}